// round 1
// baseline (speedup 1.0000x reference)
#include <cuda_runtime.h>
#include <cuda_bf16.h>

// ---------------------------------------------------------------------------
// Problem constants
// ---------------------------------------------------------------------------
#define BB    2
#define SS    1024
#define HID   4096
#define NH    64
#define NKV   8
#define HD    192
#define VD    128
#define ROT   64
#define WIN   128
#define QT    16            // queries per attention block
#define KP    161           // K smem pitch (odd -> conflict free)
#define SCALE 0.07216878364870323f   // 192^-0.5

// ---------------------------------------------------------------------------
// Scratch (static device globals; no allocations allowed)
// ---------------------------------------------------------------------------
__device__ float g_Q [(size_t)BB * SS * NH  * HD];   // (b,s,h,d)   96 MB
__device__ float g_K [(size_t)BB * SS * NKV * HD];   // (b,s,kh,d)
__device__ float g_V [(size_t)BB * SS * NKV * VD];   // (b,s,kh,d)
__device__ float g_AO[(size_t)BB * SS * NH  * VD];   // (b,s,h,d)   64 MB

// ---------------------------------------------------------------------------
// Classic 128x128x8 SGEMM, row-major A(MxK) * row-major B(KxN) -> C(MxN)
// All dims used here are multiples of 128 (M) / 128 (N) / 8 (K): no guards.
// ---------------------------------------------------------------------------
__global__ __launch_bounds__(256) void sgemm_kernel(
    const float* __restrict__ A, const float* __restrict__ B,
    float* __restrict__ C, int M, int N, int K)
{
    __shared__ float As[8][128];
    __shared__ float Bs[8][128];

    const int tid = threadIdx.x;
    const int tx = tid & 15, ty = tid >> 4;
    const int row0 = blockIdx.y * 128, col0 = blockIdx.x * 128;

    const int ar = tid >> 1, ac = (tid & 1) * 4;   // A tile load: 128 rows x 8 cols
    const int br = tid >> 5, bc = (tid & 31) * 4;  // B tile load: 8 rows x 128 cols

    const float* Ag = A + (size_t)(row0 + ar) * K + ac;
    const float* Bg = B + (size_t)br * N + col0 + bc;

    float4 a4 = *(const float4*)Ag;
    float4 b4 = *(const float4*)Bg;

    float acc[8][8];
#pragma unroll
    for (int i = 0; i < 8; i++)
#pragma unroll
        for (int j = 0; j < 8; j++) acc[i][j] = 0.f;

    for (int k0 = 0; k0 < K; k0 += 8) {
        As[ac + 0][ar] = a4.x; As[ac + 1][ar] = a4.y;
        As[ac + 2][ar] = a4.z; As[ac + 3][ar] = a4.w;
        *(float4*)&Bs[br][bc] = b4;
        __syncthreads();

        if (k0 + 8 < K) {   // prefetch next tile into registers
            a4 = *(const float4*)(Ag + k0 + 8);
            b4 = *(const float4*)(Bg + (size_t)(k0 + 8) * N);
        }

#pragma unroll
        for (int kk = 0; kk < 8; kk++) {
            float a[8], b[8];
            *(float4*)(a)     = *(const float4*)&As[kk][ty * 4];
            *(float4*)(a + 4) = *(const float4*)&As[kk][64 + ty * 4];
            *(float4*)(b)     = *(const float4*)&Bs[kk][tx * 4];
            *(float4*)(b + 4) = *(const float4*)&Bs[kk][64 + tx * 4];
#pragma unroll
            for (int i = 0; i < 8; i++)
#pragma unroll
                for (int j = 0; j < 8; j++)
                    acc[i][j] += a[i] * b[j];
        }
        __syncthreads();
    }

#pragma unroll
    for (int i = 0; i < 8; i++) {
        int r = row0 + ((i < 4) ? (ty * 4 + i) : (64 + ty * 4 + (i - 4)));
        float4 c0 = make_float4(acc[i][0], acc[i][1], acc[i][2], acc[i][3]);
        float4 c1 = make_float4(acc[i][4], acc[i][5], acc[i][6], acc[i][7]);
        *(float4*)&C[(size_t)r * N + col0 + tx * 4]      = c0;
        *(float4*)&C[(size_t)r * N + col0 + 64 + tx * 4] = c1;
    }
}

// ---------------------------------------------------------------------------
// Partial RoPE (rotate-half on first 64 dims of each 192-dim head), in place.
// cos/sin are (B,S,64) with duplicated halves: c[d+32]==c[d], s[d+32]==s[d].
// One thread per (b,s,head, d<32) pair.
// ---------------------------------------------------------------------------
__global__ __launch_bounds__(256) void rope_kernel(
    float* __restrict__ X, const float* __restrict__ cosp,
    const float* __restrict__ sinp, int nheads)
{
    int idx = blockIdx.x * blockDim.x + threadIdx.x;   // exact multiple launch
    int d  = idx & 31;
    int h  = (idx >> 5) % nheads;
    int bs = idx / (32 * nheads);                      // 0 .. B*S-1

    float* base = X + ((size_t)bs * nheads + h) * HD;
    float c = cosp[bs * ROT + d];
    float s = sinp[bs * ROT + d];
    float x1 = base[d], x2 = base[d + 32];
    base[d]      = x1 * c - x2 * s;
    base[d + 32] = x2 * c + x1 * s;
}

// ---------------------------------------------------------------------------
// Sliding-window attention with sink.
// Block = (query-tile of 16, kv-head, batch). 8 warps; each warp processes 16
// (query, q-head) pairs. K tile transposed in smem (pitch 161), V row-major.
// Softmax denominator includes exp(sink - m); sink column dropped from output.
// ---------------------------------------------------------------------------
__global__ __launch_bounds__(256) void attn_kernel(
    const float* __restrict__ Q, const float* __restrict__ K,
    const float* __restrict__ V, const float* __restrict__ sinks,
    float* __restrict__ O)
{
    extern __shared__ float sm[];
    float* ks    = sm;                    // [HD][KP]
    float* vs    = sm + HD * KP;          // [144][VD]
    float* probs = vs + 144 * VD;         // [8][160]

    const int qt = blockIdx.x, kh = blockIdx.y, b = blockIdx.z;
    const int qs0 = qt * QT;
    const int jn0 = max(0, qs0 - (WIN - 1));
    const int nk  = qs0 + QT - jn0;       // <= 143
    const int tid = threadIdx.x;

    // load K tile transposed: ks[d][j]
    for (int idx = tid; idx < nk * HD; idx += 256) {
        int j = idx / HD, d = idx - j * HD;
        ks[d * KP + j] = K[(((size_t)b * SS + jn0 + j) * NKV + kh) * HD + d];
    }
    // load V tile row-major: vs[j][d]
    for (int idx = tid; idx < nk * VD; idx += 256) {
        int j = idx >> 7, d = idx & 127;
        vs[j * VD + d] = V[(((size_t)b * SS + jn0 + j) * NKV + kh) * VD + d];
    }
    __syncthreads();

    const int w = tid >> 5, lane = tid & 31;
    float* pw = probs + w * 160;

    for (int p = w; p < 128; p += 8) {
        const int ql = p & 15, g = p >> 4;
        const int s  = qs0 + ql;
        const int h  = kh * 8 + g;
        const float* q = Q + (((size_t)b * SS + s) * NH + h) * HD;

        // dot products: lane handles keys lane, lane+32, ..., lane+128
        float dots[5] = {0.f, 0.f, 0.f, 0.f, 0.f};
        for (int d = 0; d < HD; d += 4) {
            float4 q4 = *(const float4*)(q + d);   // broadcast load (L1-hot)
#pragma unroll
            for (int u = 0; u < 4; u++) {
                float qd = (&q4.x)[u];
                const float* kr = ks + (d + u) * KP + lane;
#pragma unroll
                for (int kk = 0; kk < 5; kk++)
                    dots[kk] += qd * kr[kk * 32];
            }
        }

        // mask + scale
        float m = -1e30f;
        float sc[5];
#pragma unroll
        for (int kk = 0; kk < 5; kk++) {
            int j  = lane + kk * 32;
            int jg = jn0 + j;
            bool valid = (j < nk) && (jg <= s) && (s - jg < WIN);
            sc[kk] = valid ? dots[kk] * SCALE : -1e30f;
            m = fmaxf(m, sc[kk]);
        }
#pragma unroll
        for (int off = 16; off > 0; off >>= 1)
            m = fmaxf(m, __shfl_xor_sync(0xffffffffu, m, off));
        const float snk = sinks[h];
        m = fmaxf(m, snk);

        float ssum = 0.f;
        float pv[5];
#pragma unroll
        for (int kk = 0; kk < 5; kk++) { pv[kk] = expf(sc[kk] - m); ssum += pv[kk]; }
#pragma unroll
        for (int off = 16; off > 0; off >>= 1)
            ssum += __shfl_xor_sync(0xffffffffu, ssum, off);
        ssum += expf(snk - m);              // sink joins the denominator only
        const float inv = 1.f / ssum;

#pragma unroll
        for (int kk = 0; kk < 5; kk++)
            pw[lane + kk * 32] = pv[kk] * inv;
        __syncwarp();

        // output: lane owns 4 of 128 V dims
        float4 acc = make_float4(0.f, 0.f, 0.f, 0.f);
        const int d0 = lane * 4;
        for (int j = 0; j < nk; j++) {
            float pj  = pw[j];
            float4 v4 = *(const float4*)(vs + j * VD + d0);
            acc.x += pj * v4.x; acc.y += pj * v4.y;
            acc.z += pj * v4.z; acc.w += pj * v4.w;
        }
        *(float4*)(O + (((size_t)b * SS + s) * NH + h) * VD + d0) = acc;
        __syncwarp();   // protect pw before next pair overwrites it
    }
}

// ---------------------------------------------------------------------------
// Launcher
// ---------------------------------------------------------------------------
extern "C" void kernel_launch(void* const* d_in, const int* in_sizes, int n_in,
                              void* d_out, int out_size)
{
    const float* H     = (const float*)d_in[0];
    const float* cosp  = (const float*)d_in[1];
    const float* sinp  = (const float*)d_in[2];
    const float* Wq    = (const float*)d_in[3];
    const float* Wk    = (const float*)d_in[4];
    const float* Wv    = (const float*)d_in[5];
    const float* Wo    = (const float*)d_in[6];
    const float* sinks = (const float*)d_in[7];
    float* out = (float*)d_out;

    float *Qb, *Kb, *Vb, *AOb;
    cudaGetSymbolAddress((void**)&Qb,  g_Q);
    cudaGetSymbolAddress((void**)&Kb,  g_K);
    cudaGetSymbolAddress((void**)&Vb,  g_V);
    cudaGetSymbolAddress((void**)&AOb, g_AO);

    const int M = BB * SS;   // 2048

    // QKV projections
    sgemm_kernel<<<dim3((NH  * HD) / 128, M / 128), 256>>>(H, Wq, Qb, M, NH  * HD, HID);
    sgemm_kernel<<<dim3((NKV * HD) / 128, M / 128), 256>>>(H, Wk, Kb, M, NKV * HD, HID);
    sgemm_kernel<<<dim3((NKV * VD) / 128, M / 128), 256>>>(H, Wv, Vb, M, NKV * VD, HID);

    // partial RoPE (exact-multiple launches)
    rope_kernel<<<(M * NH  * 32) / 256, 256>>>(Qb, cosp, sinp, NH);
    rope_kernel<<<(M * NKV * 32) / 256, 256>>>(Kb, cosp, sinp, NKV);

    // attention
    const int att_smem = (HD * KP + 144 * VD + 8 * 160) * (int)sizeof(float);
    cudaFuncSetAttribute(attn_kernel,
                         cudaFuncAttributeMaxDynamicSharedMemorySize, att_smem);
    attn_kernel<<<dim3(SS / QT, NKV, BB), 256, att_smem>>>(Qb, Kb, Vb, sinks, AOb);

    // output projection
    sgemm_kernel<<<dim3(HID / 128, M / 128), 256>>>(AOb, Wo, out, M, HID, NH * VD);
}

// round 2
// speedup vs baseline: 2.0085x; 2.0085x over previous
#include <cuda_runtime.h>
#include <cuda_bf16.h>
#include <cstdint>

// ---------------------------------------------------------------------------
// Problem constants
// ---------------------------------------------------------------------------
#define BB    2
#define SS    1024
#define HID   4096
#define NH    64
#define NKV   8
#define HD    192
#define VD    128
#define ROT   64
#define WIN   128
#define QT    16
#define KP    161
#define SCALE 0.07216878364870323f   // 192^-0.5

// ---------------------------------------------------------------------------
// Scratch
// ---------------------------------------------------------------------------
__device__ float g_Q [(size_t)BB * SS * NH  * HD];
__device__ float g_K [(size_t)BB * SS * NKV * HD];
__device__ float g_V [(size_t)BB * SS * NKV * VD];
__device__ float g_AO[(size_t)BB * SS * NH  * VD];

// ---------------------------------------------------------------------------
// TF32 tensor-core GEMM: C(MxN) = A(MxK) * B(KxN), all row-major fp32.
// Block tile 128x128x32, 8 warps (2x4), warp tile 64x32, mma m16n8k8 tf32.
// Inputs converted with cvt.rna.tf32.f32 on the gmem->smem path.
// Requires: M%128==0, N%128==0, K%32==0.
// ---------------------------------------------------------------------------
#define ASZ (128 * 36)     // A smem floats per buffer (pitch 36)
#define BSZ (32 * 136)     // B smem floats per buffer (pitch 136)

__device__ __forceinline__ float to_tf32(float x) {
    float y;
    asm("cvt.rna.tf32.f32 %0, %1;" : "=f"(y) : "f"(x));
    return y;
}

__device__ __forceinline__ uint32_t smem_u32(const void* p) {
    return (uint32_t)__cvta_generic_to_shared(p);
}

__global__ __launch_bounds__(256, 1) void tf32_gemm(
    const float* __restrict__ A, const float* __restrict__ B,
    float* __restrict__ C, int M, int N, int K)
{
    extern __shared__ float sm[];
    float* As = sm;                    // [2][128][36]
    float* Bs = sm + 2 * ASZ;          // [2][32][136]

    const int tid  = threadIdx.x;
    const int lane = tid & 31, warp = tid >> 5;
    const int wm = warp & 1, wn = warp >> 1;         // warp grid 2 x 4
    const int row0 = blockIdx.y * 128, col0 = blockIdx.x * 128;

    // --- gmem staging: 4 float4 chunks per thread for each of A and B ---
    const float* Ag[4];  const float* Bg[4];
    int aso[4], bso[4];
#pragma unroll
    for (int i = 0; i < 4; i++) {
        int c  = tid + 256 * i;
        int ar = c >> 3, ac = (c & 7) * 4;           // A: 128 rows x 32 cols
        int br = c >> 5, bc = (c & 31) * 4;          // B: 32 rows x 128 cols
        Ag[i]  = A + (size_t)(row0 + ar) * K + ac;
        Bg[i]  = B + (size_t)br * N + col0 + bc;
        aso[i] = ar * 36 + ac;
        bso[i] = br * 136 + bc;
    }

    // --- fragment addresses ---
    uint32_t aAddr[4];
#pragma unroll
    for (int mt = 0; mt < 4; mt++) {
        int r = wm * 64 + mt * 16 + (lane & 15);
        int c = (lane >> 4) * 4;
        aAddr[mt] = smem_u32(As + r * 36 + c);
    }
    const float* bFrag = Bs + (lane & 3) * 136 + wn * 32 + (lane >> 2);

    float acc[4][4][4];
#pragma unroll
    for (int mt = 0; mt < 4; mt++)
#pragma unroll
        for (int nt = 0; nt < 4; nt++)
#pragma unroll
            for (int r = 0; r < 4; r++) acc[mt][nt][r] = 0.f;

    const int KT = K >> 5;
    float4 ra[4], rb[4];
#pragma unroll
    for (int i = 0; i < 4; i++) { ra[i] = *(const float4*)Ag[i]; rb[i] = *(const float4*)Bg[i]; }

    for (int kt = 0; kt < KT; kt++) {
        const int buf = kt & 1;
        float* Ab = As + buf * ASZ;
        float* Bb = Bs + buf * BSZ;

        // store staged tiles with tf32 rounding
#pragma unroll
        for (int i = 0; i < 4; i++) {
            float* pa = Ab + aso[i];
            pa[0] = to_tf32(ra[i].x); pa[1] = to_tf32(ra[i].y);
            pa[2] = to_tf32(ra[i].z); pa[3] = to_tf32(ra[i].w);
            float* pb = Bb + bso[i];
            pb[0] = to_tf32(rb[i].x); pb[1] = to_tf32(rb[i].y);
            pb[2] = to_tf32(rb[i].z); pb[3] = to_tf32(rb[i].w);
        }
        __syncthreads();

        if (kt + 1 < KT) {
#pragma unroll
            for (int i = 0; i < 4; i++) {
                ra[i] = *(const float4*)(Ag[i] + (kt + 1) * 32);
                rb[i] = *(const float4*)(Bg[i] + (size_t)(kt + 1) * 32 * N);
            }
        }

        const uint32_t abuf = buf * ASZ * 4;
        const float*   bbuf = bFrag + buf * BSZ;
#pragma unroll
        for (int ks = 0; ks < 4; ks++) {
            const int k0 = ks * 8;
            uint32_t a[4][4];
#pragma unroll
            for (int mt = 0; mt < 4; mt++)
                asm volatile(
                    "ldmatrix.sync.aligned.m8n8.x4.shared.b16 {%0,%1,%2,%3}, [%4];"
                    : "=r"(a[mt][0]), "=r"(a[mt][1]), "=r"(a[mt][2]), "=r"(a[mt][3])
                    : "r"(aAddr[mt] + abuf + k0 * 4));

            const float* bk = bbuf + k0 * 136;
#pragma unroll
            for (int nt = 0; nt < 4; nt++) {
                uint32_t b0 = __float_as_uint(bk[nt * 8]);
                uint32_t b1 = __float_as_uint(bk[nt * 8 + 4 * 136]);
#pragma unroll
                for (int mt = 0; mt < 4; mt++)
                    asm volatile(
                        "mma.sync.aligned.m16n8k8.row.col.f32.tf32.tf32.f32 "
                        "{%0,%1,%2,%3}, {%4,%5,%6,%7}, {%8,%9}, {%0,%1,%2,%3};"
                        : "+f"(acc[mt][nt][0]), "+f"(acc[mt][nt][1]),
                          "+f"(acc[mt][nt][2]), "+f"(acc[mt][nt][3])
                        : "r"(a[mt][0]), "r"(a[mt][1]), "r"(a[mt][2]), "r"(a[mt][3]),
                          "r"(b0), "r"(b1));
            }
        }
        __syncthreads();
    }

    // epilogue
#pragma unroll
    for (int mt = 0; mt < 4; mt++) {
        int r = row0 + wm * 64 + mt * 16 + (lane >> 2);
#pragma unroll
        for (int nt = 0; nt < 4; nt++) {
            int cc = col0 + wn * 32 + nt * 8 + (lane & 3) * 2;
            *(float2*)&C[(size_t)r * N + cc] =
                make_float2(acc[mt][nt][0], acc[mt][nt][1]);
            *(float2*)&C[(size_t)(r + 8) * N + cc] =
                make_float2(acc[mt][nt][2], acc[mt][nt][3]);
        }
    }
}

// ---------------------------------------------------------------------------
// Partial RoPE (rotate-half on first 64 dims), in place.
// ---------------------------------------------------------------------------
__global__ __launch_bounds__(256) void rope_kernel(
    float* __restrict__ X, const float* __restrict__ cosp,
    const float* __restrict__ sinp, int nheads)
{
    int idx = blockIdx.x * blockDim.x + threadIdx.x;
    int d  = idx & 31;
    int h  = (idx >> 5) % nheads;
    int bs = idx / (32 * nheads);

    float* base = X + ((size_t)bs * nheads + h) * HD;
    float c = cosp[bs * ROT + d];
    float s = sinp[bs * ROT + d];
    float x1 = base[d], x2 = base[d + 32];
    base[d]      = x1 * c - x2 * s;
    base[d + 32] = x2 * c + x1 * s;
}

// ---------------------------------------------------------------------------
// Sliding-window attention with sink (unchanged from round 1).
// ---------------------------------------------------------------------------
__global__ __launch_bounds__(256) void attn_kernel(
    const float* __restrict__ Q, const float* __restrict__ K,
    const float* __restrict__ V, const float* __restrict__ sinks,
    float* __restrict__ O)
{
    extern __shared__ float smn[];
    float* ks    = smn;
    float* vs    = smn + HD * KP;
    float* probs = vs + 144 * VD;

    const int qt = blockIdx.x, kh = blockIdx.y, b = blockIdx.z;
    const int qs0 = qt * QT;
    const int jn0 = max(0, qs0 - (WIN - 1));
    const int nk  = qs0 + QT - jn0;
    const int tid = threadIdx.x;

    for (int idx = tid; idx < nk * HD; idx += 256) {
        int j = idx / HD, d = idx - j * HD;
        ks[d * KP + j] = K[(((size_t)b * SS + jn0 + j) * NKV + kh) * HD + d];
    }
    for (int idx = tid; idx < nk * VD; idx += 256) {
        int j = idx >> 7, d = idx & 127;
        vs[j * VD + d] = V[(((size_t)b * SS + jn0 + j) * NKV + kh) * VD + d];
    }
    __syncthreads();

    const int w = tid >> 5, lane = tid & 31;
    float* pw = probs + w * 160;

    for (int p = w; p < 128; p += 8) {
        const int ql = p & 15, g = p >> 4;
        const int s  = qs0 + ql;
        const int h  = kh * 8 + g;
        const float* q = Q + (((size_t)b * SS + s) * NH + h) * HD;

        float dots[5] = {0.f, 0.f, 0.f, 0.f, 0.f};
        for (int d = 0; d < HD; d += 4) {
            float4 q4 = *(const float4*)(q + d);
#pragma unroll
            for (int u = 0; u < 4; u++) {
                float qd = (&q4.x)[u];
                const float* kr = ks + (d + u) * KP + lane;
#pragma unroll
                for (int kk = 0; kk < 5; kk++)
                    dots[kk] += qd * kr[kk * 32];
            }
        }

        float m = -1e30f;
        float sc[5];
#pragma unroll
        for (int kk = 0; kk < 5; kk++) {
            int j  = lane + kk * 32;
            int jg = jn0 + j;
            bool valid = (j < nk) && (jg <= s) && (s - jg < WIN);
            sc[kk] = valid ? dots[kk] * SCALE : -1e30f;
            m = fmaxf(m, sc[kk]);
        }
#pragma unroll
        for (int off = 16; off > 0; off >>= 1)
            m = fmaxf(m, __shfl_xor_sync(0xffffffffu, m, off));
        const float snk = sinks[h];
        m = fmaxf(m, snk);

        float ssum = 0.f;
        float pv[5];
#pragma unroll
        for (int kk = 0; kk < 5; kk++) { pv[kk] = expf(sc[kk] - m); ssum += pv[kk]; }
#pragma unroll
        for (int off = 16; off > 0; off >>= 1)
            ssum += __shfl_xor_sync(0xffffffffu, ssum, off);
        ssum += expf(snk - m);
        const float inv = 1.f / ssum;

#pragma unroll
        for (int kk = 0; kk < 5; kk++)
            pw[lane + kk * 32] = pv[kk] * inv;
        __syncwarp();

        float4 acc4 = make_float4(0.f, 0.f, 0.f, 0.f);
        const int d0 = lane * 4;
        for (int j = 0; j < nk; j++) {
            float pj  = pw[j];
            float4 v4 = *(const float4*)(vs + j * VD + d0);
            acc4.x += pj * v4.x; acc4.y += pj * v4.y;
            acc4.z += pj * v4.z; acc4.w += pj * v4.w;
        }
        *(float4*)(O + (((size_t)b * SS + s) * NH + h) * VD + d0) = acc4;
        __syncwarp();
    }
}

// ---------------------------------------------------------------------------
// Launcher
// ---------------------------------------------------------------------------
extern "C" void kernel_launch(void* const* d_in, const int* in_sizes, int n_in,
                              void* d_out, int out_size)
{
    const float* H     = (const float*)d_in[0];
    const float* cosp  = (const float*)d_in[1];
    const float* sinp  = (const float*)d_in[2];
    const float* Wq    = (const float*)d_in[3];
    const float* Wk    = (const float*)d_in[4];
    const float* Wv    = (const float*)d_in[5];
    const float* Wo    = (const float*)d_in[6];
    const float* sinks = (const float*)d_in[7];
    float* out = (float*)d_out;

    float *Qb, *Kb, *Vb, *AOb;
    cudaGetSymbolAddress((void**)&Qb,  g_Q);
    cudaGetSymbolAddress((void**)&Kb,  g_K);
    cudaGetSymbolAddress((void**)&Vb,  g_V);
    cudaGetSymbolAddress((void**)&AOb, g_AO);

    const int M = BB * SS;   // 2048
    const int gemm_smem = (2 * ASZ + 2 * BSZ) * (int)sizeof(float);  // 71680
    static bool attr_set = false;
    if (!attr_set) {
        cudaFuncSetAttribute(tf32_gemm,
                             cudaFuncAttributeMaxDynamicSharedMemorySize, gemm_smem);
        attr_set = true;
    }

    // QKV projections (tf32 tensor cores)
    tf32_gemm<<<dim3((NH  * HD) / 128, M / 128), 256, gemm_smem>>>(H, Wq, Qb, M, NH  * HD, HID);
    tf32_gemm<<<dim3((NKV * HD) / 128, M / 128), 256, gemm_smem>>>(H, Wk, Kb, M, NKV * HD, HID);
    tf32_gemm<<<dim3((NKV * VD) / 128, M / 128), 256, gemm_smem>>>(H, Wv, Vb, M, NKV * VD, HID);

    // partial RoPE
    rope_kernel<<<(M * NH  * 32) / 256, 256>>>(Qb, cosp, sinp, NH);
    rope_kernel<<<(M * NKV * 32) / 256, 256>>>(Kb, cosp, sinp, NKV);

    // attention
    const int att_smem = (HD * KP + 144 * VD + 8 * 160) * (int)sizeof(float);
    cudaFuncSetAttribute(attn_kernel,
                         cudaFuncAttributeMaxDynamicSharedMemorySize, att_smem);
    attn_kernel<<<dim3(SS / QT, NKV, BB), 256, att_smem>>>(Qb, Kb, Vb, sinks, AOb);

    // output projection
    tf32_gemm<<<dim3(HID / 128, M / 128), 256, gemm_smem>>>(AOb, Wo, out, M, HID, NH * VD);
}

// round 7
// speedup vs baseline: 3.4671x; 1.7262x over previous
#include <cuda_runtime.h>
#include <cuda_fp16.h>
#include <cuda_bf16.h>
#include <cstdint>

// ---------------------------------------------------------------------------
// Problem constants
// ---------------------------------------------------------------------------
#define BB    2
#define SS    1024
#define HID   4096
#define NH    64
#define NKV   8
#define HD    192
#define VD    128
#define ROT   64
#define WIN   128
#define QT    16
#define KP    161
#define SCALE 0.07216878364870323f   // 192^-0.5

#define NQ (NH * HD)     // 12288
#define NK (NKV * HD)    // 1536
#define NV (NKV * VD)    // 1024
#define NO (NH * VD)     // 8192

// ---------------------------------------------------------------------------
// Scratch (device globals; no allocations allowed)
// ---------------------------------------------------------------------------
__device__ float  g_Q [(size_t)BB * SS * NQ];     // fp32 Q (RoPE'd in place)
__device__ float  g_K [(size_t)BB * SS * NK];
__device__ float  g_V [(size_t)BB * SS * NV];
__device__ __half g_Hh [(size_t)BB * SS * HID];   // fp16 operand copies
__device__ __half g_Wqh[(size_t)HID * NQ];
__device__ __half g_Wkh[(size_t)HID * NK];
__device__ __half g_Wvh[(size_t)HID * NV];
__device__ __half g_Woh[(size_t)NO * HID];
__device__ __half g_AOh[(size_t)BB * SS * NO];    // attention output (fp16)

// ---------------------------------------------------------------------------
// Helpers
// ---------------------------------------------------------------------------
__device__ __forceinline__ uint32_t smem_u32(const void* p) {
    return (uint32_t)__cvta_generic_to_shared(p);
}

#define CP_ASYNC16(dst, src) \
    asm volatile("cp.async.cg.shared.global [%0], [%1], 16;" \
                 :: "r"(dst), "l"(src))
#define CP_COMMIT() asm volatile("cp.async.commit_group;" ::: "memory")
#define CP_WAIT2()  asm volatile("cp.async.wait_group 2;"  ::: "memory")

// ---------------------------------------------------------------------------
// fp16 mma.sync GEMM core: C(MxN fp32) = A(MxK fp16) * B(KxN fp16),
// row-major. CTA tile 128x128, K-chunk 32, 4-stage cp.async pipeline.
// 8 warps (2x4), warp tile 64x32, mma m16n8k16.
// ---------------------------------------------------------------------------
#define APITCH_B  80            // bytes per A smem row (32 fp16 + pad)
#define BPITCH_B  272           // bytes per B smem row (128 fp16 + pad)
#define A_BYTES   (128 * APITCH_B)          // 10240
#define STAGE_B   (A_BYTES + 32 * BPITCH_B) // 18944
#define GEMM_SMEM (4 * STAGE_B)             // 75776

__device__ __forceinline__ void gemm_core(
    const __half* __restrict__ Ag, int lda,
    const __half* __restrict__ Bg, int ldb,
    float* __restrict__ Cg, int ldc, int Kdim)
{
    extern __shared__ char smraw[];
    const uint32_t sb0 = smem_u32(smraw);
    const int tid = threadIdx.x, lane = tid & 31, warp = tid >> 5;
    const int wm = warp & 1, wn = warp >> 1;

    // fragment smem offsets (stage-relative)
    uint32_t aoff[4], boff[2];
#pragma unroll
    for (int mt = 0; mt < 4; mt++)
        aoff[mt] = (uint32_t)(wm * 64 + mt * 16 + (lane & 15)) * APITCH_B
                 + (uint32_t)(lane >> 4) * 16;
#pragma unroll
    for (int n2 = 0; n2 < 2; n2++)
        boff[n2] = A_BYTES + (uint32_t)(lane & 15) * BPITCH_B
                 + (uint32_t)(wn * 32 + n2 * 16) * 2
                 + (uint32_t)(lane >> 4) * 16;

    float acc[4][4][4];
#pragma unroll
    for (int mt = 0; mt < 4; mt++)
#pragma unroll
        for (int nt = 0; nt < 4; nt++)
#pragma unroll
            for (int r = 0; r < 4; r++) acc[mt][nt][r] = 0.f;

    const int KT = Kdim >> 5;

    // copy issue for k-tile ktc into stage s
    const int cm   = tid >> 2, ck16 = tid & 3;      // A: 2 chunks/thread
    const int cbk  = tid >> 4, cn16 = tid & 15;     // B: 2 chunks/thread
#define ISSUE_COPY(ktc, s) do {                                                \
        const int _k0 = (ktc) * 32;                                            \
        const uint32_t _sa = sb0 + (s) * STAGE_B;                              \
        CP_ASYNC16(_sa + cm * APITCH_B + ck16 * 16,                            \
                   Ag + (size_t)cm * lda + _k0 + ck16 * 8);                    \
        CP_ASYNC16(_sa + (cm + 64) * APITCH_B + ck16 * 16,                     \
                   Ag + (size_t)(cm + 64) * lda + _k0 + ck16 * 8);             \
        CP_ASYNC16(_sa + A_BYTES + cbk * BPITCH_B + cn16 * 16,                 \
                   Bg + (size_t)(_k0 + cbk) * ldb + cn16 * 8);                 \
        CP_ASYNC16(_sa + A_BYTES + (cbk + 16) * BPITCH_B + cn16 * 16,          \
                   Bg + (size_t)(_k0 + cbk + 16) * ldb + cn16 * 8);            \
    } while (0)

#pragma unroll
    for (int p = 0; p < 3; p++) { ISSUE_COPY(p, p); CP_COMMIT(); }

    for (int kt = 0; kt < KT; kt++) {
        CP_WAIT2();
        __syncthreads();
        const uint32_t sa = sb0 + (kt & 3) * STAGE_B;

#pragma unroll
        for (int kk = 0; kk < 2; kk++) {
            uint32_t a[4][4], b[2][4];
#pragma unroll
            for (int mt = 0; mt < 4; mt++)
                asm volatile(
                    "ldmatrix.sync.aligned.m8n8.x4.shared.b16 {%0,%1,%2,%3}, [%4];"
                    : "=r"(a[mt][0]), "=r"(a[mt][1]), "=r"(a[mt][2]), "=r"(a[mt][3])
                    : "r"(sa + aoff[mt] + kk * 32));
#pragma unroll
            for (int n2 = 0; n2 < 2; n2++)
                asm volatile(
                    "ldmatrix.sync.aligned.m8n8.x4.trans.shared.b16 {%0,%1,%2,%3}, [%4];"
                    : "=r"(b[n2][0]), "=r"(b[n2][1]), "=r"(b[n2][2]), "=r"(b[n2][3])
                    : "r"(sa + boff[n2] + kk * (16 * BPITCH_B)));
#pragma unroll
            for (int mt = 0; mt < 4; mt++)
#pragma unroll
                for (int nt = 0; nt < 4; nt++)
                    asm volatile(
                        "mma.sync.aligned.m16n8k16.row.col.f32.f16.f16.f32 "
                        "{%0,%1,%2,%3}, {%4,%5,%6,%7}, {%8,%9}, {%0,%1,%2,%3};"
                        : "+f"(acc[mt][nt][0]), "+f"(acc[mt][nt][1]),
                          "+f"(acc[mt][nt][2]), "+f"(acc[mt][nt][3])
                        : "r"(a[mt][0]), "r"(a[mt][1]), "r"(a[mt][2]), "r"(a[mt][3]),
                          "r"(b[nt >> 1][(nt & 1) * 2]), "r"(b[nt >> 1][(nt & 1) * 2 + 1]));
        }

        const int ktc = kt + 3;
        if (ktc < KT) ISSUE_COPY(ktc, ktc & 3);
        CP_COMMIT();
    }
#undef ISSUE_COPY

    // epilogue
#pragma unroll
    for (int mt = 0; mt < 4; mt++) {
        const int r = wm * 64 + mt * 16 + (lane >> 2);
#pragma unroll
        for (int nt = 0; nt < 4; nt++) {
            const int cc = wn * 32 + nt * 8 + (lane & 3) * 2;
            *(float2*)&Cg[(size_t)r * ldc + cc] =
                make_float2(acc[mt][nt][0], acc[mt][nt][1]);
            *(float2*)&Cg[(size_t)(r + 8) * ldc + cc] =
                make_float2(acc[mt][nt][2], acc[mt][nt][3]);
        }
    }
}

// fused QKV projection: one grid over the concatenated N = 12288|1536|1024
__global__ __launch_bounds__(256) void gemm_qkv(
    const __half* __restrict__ Hh,
    const __half* __restrict__ Wqh, const __half* __restrict__ Wkh,
    const __half* __restrict__ Wvh,
    float* __restrict__ Q, float* __restrict__ K, float* __restrict__ V)
{
    const int col0 = blockIdx.x * 128, row0 = blockIdx.y * 128;
    const __half* Bg; float* Cg; int ld;
    if (col0 < NQ)            { Bg = Wqh + col0;             Cg = Q + col0;             ld = NQ; }
    else if (col0 < NQ + NK)  { int c = col0 - NQ;  Bg = Wkh + c; Cg = K + c; ld = NK; }
    else                      { int c = col0 - NQ - NK; Bg = Wvh + c; Cg = V + c; ld = NV; }
    gemm_core(Hh + (size_t)row0 * HID, HID, Bg, ld,
              Cg + (size_t)row0 * ld, ld, HID);
}

// generic (output projection)
__global__ __launch_bounds__(256) void gemm_gen(
    const __half* __restrict__ Ah, const __half* __restrict__ Bh,
    float* __restrict__ C, int lda, int ldb, int Kdim)
{
    const int col0 = blockIdx.x * 128, row0 = blockIdx.y * 128;
    gemm_core(Ah + (size_t)row0 * lda, lda, Bh + col0, ldb,
              C + (size_t)row0 * ldb + col0, ldb, Kdim);
}

// ---------------------------------------------------------------------------
// fp32 -> fp16 (rn) conversion, 8 elems/thread, exact grids
// ---------------------------------------------------------------------------
__global__ __launch_bounds__(256) void f32_to_f16(
    const float* __restrict__ in, __half* __restrict__ out)
{
    const size_t i = ((size_t)blockIdx.x * 256 + threadIdx.x) * 8;
    float4 a = *(const float4*)(in + i);
    float4 b = *(const float4*)(in + i + 4);
    union { __half2 h[4]; uint4 u; } cv;
    cv.h[0] = __floats2half2_rn(a.x, a.y);
    cv.h[1] = __floats2half2_rn(a.z, a.w);
    cv.h[2] = __floats2half2_rn(b.x, b.y);
    cv.h[3] = __floats2half2_rn(b.z, b.w);
    *(uint4*)(out + i) = cv.u;
}

// ---------------------------------------------------------------------------
// Partial RoPE (rotate-half on first 64 dims), in place (fp32).
// ---------------------------------------------------------------------------
__global__ __launch_bounds__(256) void rope_kernel(
    float* __restrict__ X, const float* __restrict__ cosp,
    const float* __restrict__ sinp, int nheads)
{
    int idx = blockIdx.x * blockDim.x + threadIdx.x;
    int d  = idx & 31;
    int h  = (idx >> 5) % nheads;
    int bs = idx / (32 * nheads);

    float* base = X + ((size_t)bs * nheads + h) * HD;
    float c = cosp[bs * ROT + d];
    float s = sinp[bs * ROT + d];
    float x1 = base[d], x2 = base[d + 32];
    base[d]      = x1 * c - x2 * s;
    base[d + 32] = x2 * c + x1 * s;
}

// ---------------------------------------------------------------------------
// Sliding-window attention with sink. Output written as fp16 (GEMM operand).
// ---------------------------------------------------------------------------
__global__ __launch_bounds__(256) void attn_kernel(
    const float* __restrict__ Q, const float* __restrict__ K,
    const float* __restrict__ V, const float* __restrict__ sinks,
    __half* __restrict__ O)
{
    extern __shared__ float smn[];
    float* ks    = smn;                    // [HD][KP]
    float* vs    = smn + HD * KP;          // [144][VD]
    float* probs = vs + 144 * VD;          // [8][160]

    const int qt = blockIdx.x, kh = blockIdx.y, b = blockIdx.z;
    const int qs0 = qt * QT;
    const int jn0 = max(0, qs0 - (WIN - 1));
    const int nk  = qs0 + QT - jn0;
    const int tid = threadIdx.x;

    for (int idx = tid; idx < nk * HD; idx += 256) {
        int j = idx / HD, d = idx - j * HD;
        ks[d * KP + j] = K[(((size_t)b * SS + jn0 + j) * NKV + kh) * HD + d];
    }
    for (int idx = tid; idx < nk * VD; idx += 256) {
        int j = idx >> 7, d = idx & 127;
        vs[j * VD + d] = V[(((size_t)b * SS + jn0 + j) * NKV + kh) * VD + d];
    }
    __syncthreads();

    const int w = tid >> 5, lane = tid & 31;
    float* pw = probs + w * 160;

    for (int p = w; p < 128; p += 8) {
        const int ql = p & 15, g = p >> 4;
        const int s  = qs0 + ql;
        const int h  = kh * 8 + g;
        const float* q = Q + (((size_t)b * SS + s) * NH + h) * HD;

        float dots[5] = {0.f, 0.f, 0.f, 0.f, 0.f};
        for (int d = 0; d < HD; d += 4) {
            float4 q4 = *(const float4*)(q + d);
#pragma unroll
            for (int u = 0; u < 4; u++) {
                float qd = (&q4.x)[u];
                const float* kr = ks + (d + u) * KP + lane;
#pragma unroll
                for (int kk = 0; kk < 5; kk++)
                    dots[kk] += qd * kr[kk * 32];
            }
        }

        float m = -1e30f;
        float sc[5];
#pragma unroll
        for (int kk = 0; kk < 5; kk++) {
            int j  = lane + kk * 32;
            int jg = jn0 + j;
            bool valid = (j < nk) && (jg <= s) && (s - jg < WIN);
            sc[kk] = valid ? dots[kk] * SCALE : -1e30f;
            m = fmaxf(m, sc[kk]);
        }
#pragma unroll
        for (int off = 16; off > 0; off >>= 1)
            m = fmaxf(m, __shfl_xor_sync(0xffffffffu, m, off));
        const float snk = sinks[h];
        m = fmaxf(m, snk);

        float ssum = 0.f;
        float pv[5];
#pragma unroll
        for (int kk = 0; kk < 5; kk++) { pv[kk] = expf(sc[kk] - m); ssum += pv[kk]; }
#pragma unroll
        for (int off = 16; off > 0; off >>= 1)
            ssum += __shfl_xor_sync(0xffffffffu, ssum, off);
        ssum += expf(snk - m);
        const float inv = 1.f / ssum;

#pragma unroll
        for (int kk = 0; kk < 5; kk++)
            pw[lane + kk * 32] = pv[kk] * inv;
        __syncwarp();

        float4 acc4 = make_float4(0.f, 0.f, 0.f, 0.f);
        const int d0 = lane * 4;
        for (int j = 0; j < nk; j++) {
            float pj  = pw[j];
            float4 v4 = *(const float4*)(vs + j * VD + d0);
            acc4.x += pj * v4.x; acc4.y += pj * v4.y;
            acc4.z += pj * v4.z; acc4.w += pj * v4.w;
        }
        __half* op = O + (((size_t)b * SS + s) * NH + h) * VD + d0;
        *(__half2*)op       = __floats2half2_rn(acc4.x, acc4.y);
        *(__half2*)(op + 2) = __floats2half2_rn(acc4.z, acc4.w);
        __syncwarp();
    }
}

// ---------------------------------------------------------------------------
// Launcher
// ---------------------------------------------------------------------------
extern "C" void kernel_launch(void* const* d_in, const int* in_sizes, int n_in,
                              void* d_out, int out_size)
{
    const float* H     = (const float*)d_in[0];
    const float* cosp  = (const float*)d_in[1];
    const float* sinp  = (const float*)d_in[2];
    const float* Wq    = (const float*)d_in[3];
    const float* Wk    = (const float*)d_in[4];
    const float* Wv    = (const float*)d_in[5];
    const float* Wo    = (const float*)d_in[6];
    const float* sinks = (const float*)d_in[7];
    float* out = (float*)d_out;

    float *Qb, *Kb, *Vb;
    __half *Hh, *Wqh, *Wkh, *Wvh, *Woh, *AOh;
    cudaGetSymbolAddress((void**)&Qb,  g_Q);
    cudaGetSymbolAddress((void**)&Kb,  g_K);
    cudaGetSymbolAddress((void**)&Vb,  g_V);
    cudaGetSymbolAddress((void**)&Hh,  g_Hh);
    cudaGetSymbolAddress((void**)&Wqh, g_Wqh);
    cudaGetSymbolAddress((void**)&Wkh, g_Wkh);
    cudaGetSymbolAddress((void**)&Wvh, g_Wvh);
    cudaGetSymbolAddress((void**)&Woh, g_Woh);
    cudaGetSymbolAddress((void**)&AOh, g_AOh);

    const int M = BB * SS;   // 2048
    static bool attr_set = false;
    if (!attr_set) {
        cudaFuncSetAttribute(gemm_qkv,
                             cudaFuncAttributeMaxDynamicSharedMemorySize, GEMM_SMEM);
        cudaFuncSetAttribute(gemm_gen,
                             cudaFuncAttributeMaxDynamicSharedMemorySize, GEMM_SMEM);
        attr_set = true;
    }

    // fp32 -> fp16 operand conversion
    f32_to_f16<<<(M * HID)   / 2048, 256>>>(H,  Hh);
    f32_to_f16<<<(HID * NQ)  / 2048, 256>>>(Wq, Wqh);
    f32_to_f16<<<(HID * NK)  / 2048, 256>>>(Wk, Wkh);
    f32_to_f16<<<(HID * NV)  / 2048, 256>>>(Wv, Wvh);
    f32_to_f16<<<(NO * HID)  / 2048, 256>>>(Wo, Woh);

    // fused QKV projection
    gemm_qkv<<<dim3((NQ + NK + NV) / 128, M / 128), 256, GEMM_SMEM>>>(
        Hh, Wqh, Wkh, Wvh, Qb, Kb, Vb);

    // partial RoPE
    rope_kernel<<<(M * NH  * 32) / 256, 256>>>(Qb, cosp, sinp, NH);
    rope_kernel<<<(M * NKV * 32) / 256, 256>>>(Kb, cosp, sinp, NKV);

    // attention -> fp16 AO
    const int att_smem = (HD * KP + 144 * VD + 8 * 160) * (int)sizeof(float);
    cudaFuncSetAttribute(attn_kernel,
                         cudaFuncAttributeMaxDynamicSharedMemorySize, att_smem);
    attn_kernel<<<dim3(SS / QT, NKV, BB), 256, att_smem>>>(Qb, Kb, Vb, sinks, AOh);

    // output projection
    gemm_gen<<<dim3(HID / 128, M / 128), 256, GEMM_SMEM>>>(
        AOh, Woh, out, NO, HID, NO);
}